// round 4
// baseline (speedup 1.0000x reference)
#include <cuda_runtime.h>
#include <cuda_bf16.h>
#include <cstdint>
#include <math.h>

#define B_ 16
#define S_ 4096
#define H_ 1024
#define C_ 64

// Scratch: fp32 scores, bf16 hi/lo factor arrays, bf16 hi/lo querys
__device__ __align__(16) float g_scores[B_ * C_ * S_];                // 16 MB
__device__ __align__(16) __nv_bfloat16 g_fhi[B_ * C_ * S_];           // 8 MB
__device__ __align__(16) __nv_bfloat16 g_flo[B_ * C_ * S_];           // 8 MB
__device__ __align__(16) __nv_bfloat16 g_qhi[C_ * H_];                // 128 KB
__device__ __align__(16) __nv_bfloat16 g_qlo[C_ * H_];                // 128 KB

// ===========================================================================
// Helpers
// ===========================================================================
__device__ __forceinline__ uint32_t smem_u32(const void* p) {
    uint32_t a;
    asm("{ .reg .u64 t; cvta.to.shared.u64 t, %1; cvt.u32.u64 %0, t; }"
        : "=r"(a) : "l"(p));
    return a;
}

// pack (f0 -> low half, f1 -> high half) as bf16x2
__device__ __forceinline__ uint32_t pack_bf2(float f0, float f1) {
    uint32_t r;
    asm("cvt.rn.bf16x2.f32 %0, %2, %1;" : "=r"(r) : "f"(f0), "f"(f1));
    return r;
}

// split float4 into hi-bf16x4 and lo-bf16x4 (lo = x - hi, rounded to bf16)
__device__ __forceinline__ void cvt_split(float4 v, unsigned long long& hh,
                                          unsigned long long& ll) {
    uint32_t h01 = pack_bf2(v.x, v.y);
    uint32_t h23 = pack_bf2(v.z, v.w);
    float l0 = v.x - __uint_as_float(h01 << 16);
    float l1 = v.y - __uint_as_float(h01 & 0xffff0000u);
    float l2 = v.z - __uint_as_float(h23 << 16);
    float l3 = v.w - __uint_as_float(h23 & 0xffff0000u);
    hh = ((unsigned long long)h23 << 32) | h01;
    ll = ((unsigned long long)pack_bf2(l2, l3) << 32) | pack_bf2(l0, l1);
}

__device__ __forceinline__ void st64(uint32_t a, unsigned long long v) {
    asm volatile("st.shared.b64 [%0], %1;" :: "r"(a), "l"(v) : "memory");
}

__device__ __forceinline__ void cp16(uint32_t dst, const void* src) {
    asm volatile("cp.async.cg.shared.global [%0], [%1], 16;"
                 :: "r"(dst), "l"(__cvta_generic_to_global(src)) : "memory");
}
#define CP_COMMIT() asm volatile("cp.async.commit_group;" ::: "memory")
#define CP_WAIT0()  asm volatile("cp.async.wait_group 0;" ::: "memory")

#define LDSM_X4(r0, r1, r2, r3, a) \
    asm volatile("ldmatrix.sync.aligned.m8n8.x4.shared.b16 {%0,%1,%2,%3}, [%4];" \
                 : "=r"(r0), "=r"(r1), "=r"(r2), "=r"(r3) : "r"(a))

#define LDSM_X4T(r0, r1, r2, r3, a) \
    asm volatile("ldmatrix.sync.aligned.m8n8.x4.trans.shared.b16 {%0,%1,%2,%3}, [%4];" \
                 : "=r"(r0), "=r"(r1), "=r"(r2), "=r"(r3) : "r"(a))

#define MMA_BF16(d, a, b0, b1) \
    asm volatile("mma.sync.aligned.m16n8k16.row.col.f32.bf16.bf16.f32 " \
                 "{%0,%1,%2,%3}, {%4,%5,%6,%7}, {%8,%9}, {%0,%1,%2,%3};" \
                 : "+f"((d)[0]), "+f"((d)[1]), "+f"((d)[2]), "+f"((d)[3]) \
                 : "r"((a)[0]), "r"((a)[1]), "r"((a)[2]), "r"((a)[3]), \
                   "r"(b0), "r"(b1))

// ===========================================================================
// K0: pre-split querys [C][H] fp32 -> hi/lo bf16
// ===========================================================================
__global__ __launch_bounds__(256) void k0_prep(const float* __restrict__ querys) {
    const int c = blockIdx.x;
    const int tid = threadIdx.x;
    float4 v = *reinterpret_cast<const float4*>(querys + (size_t)c * H_ + tid * 4);
    unsigned long long hh, ll;
    cvt_split(v, hh, ll);
    *reinterpret_cast<unsigned long long*>(g_qhi + (size_t)c * H_ + tid * 4) = hh;
    *reinterpret_cast<unsigned long long*>(g_qlo + (size_t)c * H_ + tid * 4) = ll;
}

// ===========================================================================
// K1: scores[b][c][s] = sum_h hidden[b][s][h] * querys[c][h]
// D[s,c]: M=128 s, N=64 c, K=1024 h (16 chunks of 64).
// A = hidden (LDG+cvt+STS). B = pre-split querys hi/lo via cp.async.
// ===========================================================================
#define K1_STRIDE 144                      // bytes per smem row (72 bf16)
#define K1_A_SZ   (128 * K1_STRIDE)        // 18432
#define K1_B_SZ   (64 * K1_STRIDE)         // 9216
#define K1_BUF    (2 * K1_A_SZ + 2 * K1_B_SZ)  // 55296
#define K1_SMEM   (2 * K1_BUF)             // 110592

__global__ void __launch_bounds__(256, 2) k1_mma(const float* __restrict__ hidden) {
    extern __shared__ char smem[];
    const uint32_t sb = smem_u32(smem);
    const int tid = threadIdx.x, lane = tid & 31, wid = tid >> 5;
    const int b = blockIdx.y, s0 = blockIdx.x * 128;
    const int mrow0 = (wid >> 1) * 32, ncol0 = (wid & 1) * 32;
    const uint32_t rowoff = (lane & 7) + ((lane >> 3) & 1) * 8;
    const uint32_t coloff = (lane >> 4) * 8;
    const int g = lane >> 2, tg = lane & 3;

    const float* hbase = hidden + ((size_t)b * S_ + s0) * H_;

    float4 hv[8];
    float acc[2][4][4] = {};

    auto LDGA = [&](int ch) {
        const int h0 = ch * 64;
#pragma unroll
        for (int t = 0; t < 8; t++) {
            int idx = tid + t * 256, row = idx >> 4, f4 = idx & 15;
            hv[t] = *reinterpret_cast<const float4*>(hbase + (size_t)row * H_ + h0 + f4 * 4);
        }
    };

    auto CPB = [&](int ch, int buf) {
        const uint32_t bHi = sb + buf * K1_BUF + 2 * K1_A_SZ;
        const uint32_t bLo = bHi + K1_B_SZ;
        const int h0 = ch * 64;
#pragma unroll
        for (int t = 0; t < 2; t++) {
            int idx = tid + t * 256;          // 0..511
            int row = idx >> 3, k = idx & 7;
            uint32_t doff = row * K1_STRIDE + k * 16;
            const char* shi = reinterpret_cast<const char*>(g_qhi + (size_t)row * H_ + h0) + k * 16;
            const char* slo = reinterpret_cast<const char*>(g_qlo + (size_t)row * H_ + h0) + k * 16;
            cp16(bHi + doff, shi);
            cp16(bLo + doff, slo);
        }
        CP_COMMIT();
    };

    auto STSA = [&](int buf) {
        const uint32_t aHi = sb + buf * K1_BUF;
        const uint32_t aLo = aHi + K1_A_SZ;
#pragma unroll
        for (int t = 0; t < 8; t++) {
            int idx = tid + t * 256, row = idx >> 4, f4 = idx & 15;
            unsigned long long hh, ll;
            cvt_split(hv[t], hh, ll);
            uint32_t off = row * K1_STRIDE + f4 * 8;
            st64(aHi + off, hh);
            st64(aLo + off, ll);
        }
    };

    auto COMPUTE = [&](int buf) {
        const uint32_t aHi = sb + buf * K1_BUF;
        const uint32_t aLo = aHi + K1_A_SZ;
        const uint32_t bHi = aLo + K1_A_SZ;
        const uint32_t bLo = bHi + K1_B_SZ;
#pragma unroll
        for (int k16 = 0; k16 < 4; k16++) {
            const uint32_t kb = (k16 * 16 + coloff) * 2;
            uint32_t ah[2][4], al[2][4];
#pragma unroll
            for (int mi = 0; mi < 2; mi++) {
                uint32_t off = (mrow0 + mi * 16 + rowoff) * K1_STRIDE + kb;
                LDSM_X4(ah[mi][0], ah[mi][1], ah[mi][2], ah[mi][3], aHi + off);
                LDSM_X4(al[mi][0], al[mi][1], al[mi][2], al[mi][3], aLo + off);
            }
            uint32_t bh[4][2], bl[4][2];
#pragma unroll
            for (int nh = 0; nh < 2; nh++) {
                uint32_t off = (ncol0 + nh * 16 + rowoff) * K1_STRIDE + kb;
                uint32_t r0, r1, r2, r3;
                LDSM_X4(r0, r1, r2, r3, bHi + off);
                bh[nh * 2][0] = r0; bh[nh * 2][1] = r2;
                bh[nh * 2 + 1][0] = r1; bh[nh * 2 + 1][1] = r3;
                LDSM_X4(r0, r1, r2, r3, bLo + off);
                bl[nh * 2][0] = r0; bl[nh * 2][1] = r2;
                bl[nh * 2 + 1][0] = r1; bl[nh * 2 + 1][1] = r3;
            }
#pragma unroll
            for (int mi = 0; mi < 2; mi++)
#pragma unroll
                for (int ni = 0; ni < 4; ni++) {
                    MMA_BF16(acc[mi][ni], ah[mi], bh[ni][0], bh[ni][1]);
                    MMA_BF16(acc[mi][ni], ah[mi], bl[ni][0], bl[ni][1]);
                    MMA_BF16(acc[mi][ni], al[mi], bh[ni][0], bh[ni][1]);
                }
        }
    };

    // Prologue
    LDGA(0);
    CPB(0, 0);
    STSA(0);
    CP_WAIT0();
    __syncthreads();

#pragma unroll 1
    for (int ch = 0; ch < 16; ch++) {
        if (ch < 15) {
            CPB(ch + 1, (ch + 1) & 1);
            LDGA(ch + 1);
        }
        COMPUTE(ch & 1);
        if (ch < 15) STSA((ch + 1) & 1);
        CP_WAIT0();
        __syncthreads();
    }

    // Epilogue: transpose through smem -> coalesced [c][s] stores
    float* T = reinterpret_cast<float*>(smem);  // 64 x 132
#pragma unroll
    for (int mi = 0; mi < 2; mi++)
#pragma unroll
        for (int ni = 0; ni < 4; ni++) {
            int srow = mrow0 + mi * 16 + g;
            int ccol = ncol0 + ni * 8 + tg * 2;
            T[ccol * 132 + srow] = acc[mi][ni][0];
            T[(ccol + 1) * 132 + srow] = acc[mi][ni][1];
            T[ccol * 132 + srow + 8] = acc[mi][ni][2];
            T[(ccol + 1) * 132 + srow + 8] = acc[mi][ni][3];
        }
    __syncthreads();
    float* gs = g_scores + (size_t)b * C_ * S_ + s0;
#pragma unroll
    for (int t = 0; t < 8; t++) {
        int idx = tid + t * 256, row = idx >> 5, f4 = idx & 31;
        float4 v = *reinterpret_cast<const float4*>(&T[row * 132 + f4 * 4]);
        *reinterpret_cast<float4*>(gs + (size_t)row * S_ + f4 * 4) = v;
    }
}

// ===========================================================================
// K2: softmax over s for each of B*C rows; writes hi/lo bf16 factors.
// ===========================================================================
__global__ __launch_bounds__(256) void k2_softmax() {
    __shared__ float red_max[8];
    __shared__ float red_sum[8];

    const size_t rowoff = (size_t)blockIdx.x * S_;
    const float* row = g_scores + rowoff;
    const int tid = threadIdx.x;

    float4 v[4];
    float mx = -1e30f;
#pragma unroll
    for (int t = 0; t < 4; t++) {
        v[t] = reinterpret_cast<const float4*>(row)[tid + t * 256];
        mx = fmaxf(mx, fmaxf(fmaxf(v[t].x, v[t].y), fmaxf(v[t].z, v[t].w)));
    }
#pragma unroll
    for (int o = 16; o > 0; o >>= 1) mx = fmaxf(mx, __shfl_xor_sync(0xffffffffu, mx, o));
    if ((tid & 31) == 0) red_max[tid >> 5] = mx;
    __syncthreads();
    mx = red_max[0];
#pragma unroll
    for (int w = 1; w < 8; w++) mx = fmaxf(mx, red_max[w]);

    float s = 0.0f;
#pragma unroll
    for (int t = 0; t < 4; t++) {
        v[t].x = expf(v[t].x - mx);
        v[t].y = expf(v[t].y - mx);
        v[t].z = expf(v[t].z - mx);
        v[t].w = expf(v[t].w - mx);
        s += v[t].x + v[t].y + v[t].z + v[t].w;
    }
#pragma unroll
    for (int o = 16; o > 0; o >>= 1) s += __shfl_xor_sync(0xffffffffu, s, o);
    if ((tid & 31) == 0) red_sum[tid >> 5] = s;
    __syncthreads();
    s = red_sum[0];
#pragma unroll
    for (int w = 1; w < 8; w++) s += red_sum[w];

    const float inv = 1.0f / s;
#pragma unroll
    for (int t = 0; t < 4; t++) {
        v[t].x *= inv; v[t].y *= inv; v[t].z *= inv; v[t].w *= inv;
        unsigned long long hh, ll;
        cvt_split(v[t], hh, ll);
        size_t off = rowoff + (size_t)(tid + t * 256) * 4;
        *reinterpret_cast<unsigned long long*>(g_fhi + off) = hh;
        *reinterpret_cast<unsigned long long*>(g_flo + off) = ll;
    }
}

// ===========================================================================
// K3: out[b][c*H+h] = sum_s factor[b][c][s] * hidden[b][s][h]
// D[c,h]: M=64 c, N=128 h, K=4096 s (64 chunks of 64).
// A = pre-split factors hi/lo via cp.async. B = hidden (LDG+cvt+STS, ldmatrix.trans).
// ===========================================================================
#define K3_ASTR 144                        // factor row stride bytes (72 bf16)
#define K3_BSTR 272                        // hidden row stride bytes (136 bf16)
#define K3_A_SZ (64 * K3_ASTR)             // 9216
#define K3_B_SZ (64 * K3_BSTR)             // 17408
#define K3_BUF  (2 * K3_A_SZ + 2 * K3_B_SZ)   // 53248
#define K3_SMEM (2 * K3_BUF)               // 106496

__global__ void __launch_bounds__(256, 2) k3_mma(const float* __restrict__ hidden,
                                                 float* __restrict__ out) {
    extern __shared__ char smem[];
    const uint32_t sb = smem_u32(smem);
    const int tid = threadIdx.x, lane = tid & 31, wid = tid >> 5;
    const int b = blockIdx.y, h0 = blockIdx.x * 128;
    const int mrow0 = (wid >> 2) * 32, ncol0 = (wid & 3) * 32;
    const uint32_t rowoff = (lane & 7) + ((lane >> 3) & 1) * 8;
    const uint32_t coloff = (lane >> 4) * 8;
    const int g = lane >> 2, tg = lane & 3;

    const __nv_bfloat16* fhib = g_fhi + (size_t)b * C_ * S_;
    const __nv_bfloat16* flob = g_flo + (size_t)b * C_ * S_;
    const float* hbase = hidden + (size_t)b * S_ * H_;

    float4 hv[8];
    float acc[2][4][4] = {};

    auto CPA = [&](int ch, int buf) {
        const uint32_t aHi = sb + buf * K3_BUF;
        const uint32_t aLo = aHi + K3_A_SZ;
        const int s0 = ch * 64;
#pragma unroll
        for (int t = 0; t < 2; t++) {
            int idx = tid + t * 256;          // 0..511
            int row = idx >> 3, k = idx & 7;
            uint32_t doff = row * K3_ASTR + k * 16;
            const char* shi = reinterpret_cast<const char*>(fhib + (size_t)row * S_ + s0) + k * 16;
            const char* slo = reinterpret_cast<const char*>(flob + (size_t)row * S_ + s0) + k * 16;
            cp16(aHi + doff, shi);
            cp16(aLo + doff, slo);
        }
        CP_COMMIT();
    };

    auto LDGB = [&](int ch) {
        const int s0 = ch * 64;
#pragma unroll
        for (int t = 0; t < 8; t++) {
            int idx = tid + t * 256, row = idx >> 5, f4 = idx & 31;
            hv[t] = *reinterpret_cast<const float4*>(hbase + (size_t)(s0 + row) * H_ + h0 + f4 * 4);
        }
    };

    auto STSB = [&](int buf) {
        const uint32_t bHi = sb + buf * K3_BUF + 2 * K3_A_SZ;
        const uint32_t bLo = bHi + K3_B_SZ;
#pragma unroll
        for (int t = 0; t < 8; t++) {
            int idx = tid + t * 256, row = idx >> 5, f4 = idx & 31;
            unsigned long long hh, ll;
            cvt_split(hv[t], hh, ll);
            uint32_t off = row * K3_BSTR + f4 * 8;
            st64(bHi + off, hh);
            st64(bLo + off, ll);
        }
    };

    auto COMPUTE = [&](int buf) {
        const uint32_t aHi = sb + buf * K3_BUF;
        const uint32_t aLo = aHi + K3_A_SZ;
        const uint32_t bHi = aLo + K3_A_SZ;
        const uint32_t bLo = bHi + K3_B_SZ;
#pragma unroll
        for (int k16 = 0; k16 < 4; k16++) {
            uint32_t ah[2][4], al[2][4];
#pragma unroll
            for (int mi = 0; mi < 2; mi++) {
                uint32_t off = (mrow0 + mi * 16 + rowoff) * K3_ASTR + (k16 * 16 + coloff) * 2;
                LDSM_X4(ah[mi][0], ah[mi][1], ah[mi][2], ah[mi][3], aHi + off);
                LDSM_X4(al[mi][0], al[mi][1], al[mi][2], al[mi][3], aLo + off);
            }
            uint32_t bh[4][2], bl[4][2];
#pragma unroll
            for (int nh = 0; nh < 2; nh++) {
                uint32_t off = (k16 * 16 + rowoff) * K3_BSTR + (ncol0 + nh * 16 + coloff) * 2;
                uint32_t r0, r1, r2, r3;
                LDSM_X4T(r0, r1, r2, r3, bHi + off);
                bh[nh * 2][0] = r0; bh[nh * 2][1] = r1;
                bh[nh * 2 + 1][0] = r2; bh[nh * 2 + 1][1] = r3;
                LDSM_X4T(r0, r1, r2, r3, bLo + off);
                bl[nh * 2][0] = r0; bl[nh * 2][1] = r1;
                bl[nh * 2 + 1][0] = r2; bl[nh * 2 + 1][1] = r3;
            }
#pragma unroll
            for (int mi = 0; mi < 2; mi++)
#pragma unroll
                for (int ni = 0; ni < 4; ni++) {
                    MMA_BF16(acc[mi][ni], ah[mi], bh[ni][0], bh[ni][1]);
                    MMA_BF16(acc[mi][ni], ah[mi], bl[ni][0], bl[ni][1]);
                    MMA_BF16(acc[mi][ni], al[mi], bh[ni][0], bh[ni][1]);
                }
        }
    };

    // Prologue
    CPA(0, 0);
    LDGB(0);
    STSB(0);
    CP_WAIT0();
    __syncthreads();

#pragma unroll 1
    for (int ch = 0; ch < 64; ch++) {
        if (ch < 63) {
            CPA(ch + 1, (ch + 1) & 1);
            LDGB(ch + 1);
        }
        COMPUTE(ch & 1);
        if (ch < 63) STSB((ch + 1) & 1);
        CP_WAIT0();
        __syncthreads();
    }

    // Epilogue: transpose through smem -> coalesced [c][h] stores
    float* T = reinterpret_cast<float*>(smem);  // 64 x 132
#pragma unroll
    for (int mi = 0; mi < 2; mi++)
#pragma unroll
        for (int ni = 0; ni < 4; ni++) {
            int crow = mrow0 + mi * 16 + g;
            int hcol = ncol0 + ni * 8 + tg * 2;
            T[crow * 132 + hcol] = acc[mi][ni][0];
            T[crow * 132 + hcol + 1] = acc[mi][ni][1];
            T[(crow + 8) * 132 + hcol] = acc[mi][ni][2];
            T[(crow + 8) * 132 + hcol + 1] = acc[mi][ni][3];
        }
    __syncthreads();
    float* ob = out + (size_t)b * (C_ * H_) + h0;
#pragma unroll
    for (int t = 0; t < 8; t++) {
        int idx = tid + t * 256, row = idx >> 5, f4 = idx & 31;
        float4 v = *reinterpret_cast<const float4*>(&T[row * 132 + f4 * 4]);
        *reinterpret_cast<float4*>(ob + (size_t)row * H_ + f4 * 4) = v;
    }
}

// ---------------------------------------------------------------------------
extern "C" void kernel_launch(void* const* d_in, const int* in_sizes, int n_in,
                              void* d_out, int out_size) {
    const float* hidden = (const float*)d_in[0];   // [B, S, H] fp32
    const float* querys = (const float*)d_in[1];   // [C, H]    fp32
    float* out = (float*)d_out;                    // [B, C*H]  fp32

    cudaFuncSetAttribute(k1_mma, cudaFuncAttributeMaxDynamicSharedMemorySize, K1_SMEM);
    cudaFuncSetAttribute(k3_mma, cudaFuncAttributeMaxDynamicSharedMemorySize, K3_SMEM);

    k0_prep<<<C_, 256>>>(querys);

    dim3 g1(S_ / 128, B_);
    k1_mma<<<g1, 256, K1_SMEM>>>(hidden);

    k2_softmax<<<B_ * C_, 256>>>();

    dim3 g3(H_ / 128, B_);
    k3_mma<<<g3, 256, K3_SMEM>>>(hidden, out);
}

// round 5
// speedup vs baseline: 1.0960x; 1.0960x over previous
#include <cuda_runtime.h>
#include <cuda_bf16.h>
#include <cstdint>
#include <math.h>

#define B_ 16
#define S_ 4096
#define H_ 1024
#define C_ 64

// Scratch: fp32 scores, bf16 hi/lo factor arrays, bf16 hi/lo querys
__device__ __align__(16) float g_scores[B_ * C_ * S_];                // 16 MB
__device__ __align__(16) __nv_bfloat16 g_fhi[B_ * C_ * S_];           // 8 MB
__device__ __align__(16) __nv_bfloat16 g_flo[B_ * C_ * S_];           // 8 MB
__device__ __align__(16) __nv_bfloat16 g_qhi[C_ * H_];                // 128 KB
__device__ __align__(16) __nv_bfloat16 g_qlo[C_ * H_];                // 128 KB

// ===========================================================================
// Helpers
// ===========================================================================
__device__ __forceinline__ uint32_t smem_u32(const void* p) {
    uint32_t a;
    asm("{ .reg .u64 t; cvta.to.shared.u64 t, %1; cvt.u32.u64 %0, t; }"
        : "=r"(a) : "l"(p));
    return a;
}

// pack (f0 -> low half, f1 -> high half) as bf16x2
__device__ __forceinline__ uint32_t pack_bf2(float f0, float f1) {
    uint32_t r;
    asm("cvt.rn.bf16x2.f32 %0, %2, %1;" : "=r"(r) : "f"(f0), "f"(f1));
    return r;
}

// split float4 into hi-bf16x4 and lo-bf16x4 (lo = x - hi, rounded to bf16)
__device__ __forceinline__ void cvt_split(float4 v, unsigned long long& hh,
                                          unsigned long long& ll) {
    uint32_t h01 = pack_bf2(v.x, v.y);
    uint32_t h23 = pack_bf2(v.z, v.w);
    float l0 = v.x - __uint_as_float(h01 << 16);
    float l1 = v.y - __uint_as_float(h01 & 0xffff0000u);
    float l2 = v.z - __uint_as_float(h23 << 16);
    float l3 = v.w - __uint_as_float(h23 & 0xffff0000u);
    hh = ((unsigned long long)h23 << 32) | h01;
    ll = ((unsigned long long)pack_bf2(l2, l3) << 32) | pack_bf2(l0, l1);
}

__device__ __forceinline__ void st64(uint32_t a, unsigned long long v) {
    asm volatile("st.shared.b64 [%0], %1;" :: "r"(a), "l"(v) : "memory");
}

__device__ __forceinline__ void cp16(uint32_t dst, const void* src) {
    asm volatile("cp.async.cg.shared.global [%0], [%1], 16;"
                 :: "r"(dst), "l"(__cvta_generic_to_global(src)) : "memory");
}
#define CP_COMMIT() asm volatile("cp.async.commit_group;" ::: "memory")
#define CP_WAIT0()  asm volatile("cp.async.wait_group 0;" ::: "memory")

#define LDSM_X4(r0, r1, r2, r3, a) \
    asm volatile("ldmatrix.sync.aligned.m8n8.x4.shared.b16 {%0,%1,%2,%3}, [%4];" \
                 : "=r"(r0), "=r"(r1), "=r"(r2), "=r"(r3) : "r"(a))

#define LDSM_X4T(r0, r1, r2, r3, a) \
    asm volatile("ldmatrix.sync.aligned.m8n8.x4.trans.shared.b16 {%0,%1,%2,%3}, [%4];" \
                 : "=r"(r0), "=r"(r1), "=r"(r2), "=r"(r3) : "r"(a))

#define MMA_BF16(d, a, b0, b1) \
    asm volatile("mma.sync.aligned.m16n8k16.row.col.f32.bf16.bf16.f32 " \
                 "{%0,%1,%2,%3}, {%4,%5,%6,%7}, {%8,%9}, {%0,%1,%2,%3};" \
                 : "+f"((d)[0]), "+f"((d)[1]), "+f"((d)[2]), "+f"((d)[3]) \
                 : "r"((a)[0]), "r"((a)[1]), "r"((a)[2]), "r"((a)[3]), \
                   "r"(b0), "r"(b1))

// ===========================================================================
// K0: pre-split querys [C][H] fp32 -> hi/lo bf16
// ===========================================================================
__global__ __launch_bounds__(256) void k0_prep(const float* __restrict__ querys) {
    const int c = blockIdx.x;
    const int tid = threadIdx.x;
    float4 v = *reinterpret_cast<const float4*>(querys + (size_t)c * H_ + tid * 4);
    unsigned long long hh, ll;
    cvt_split(v, hh, ll);
    *reinterpret_cast<unsigned long long*>(g_qhi + (size_t)c * H_ + tid * 4) = hh;
    *reinterpret_cast<unsigned long long*>(g_qlo + (size_t)c * H_ + tid * 4) = ll;
}

// ===========================================================================
// K1: scores[b][c][s] = sum_h hidden[b][s][h] * querys[c][h]
// D[s,c]: M=128 s, N=64 c, K=1024 h (16 chunks of 64).
// A = hidden (LDG+cvt+STS). B = pre-split querys hi/lo via cp.async.
// ===========================================================================
#define K1_STRIDE 144                      // bytes per smem row (72 bf16)
#define K1_A_SZ   (128 * K1_STRIDE)        // 18432
#define K1_B_SZ   (64 * K1_STRIDE)         // 9216
#define K1_BUF    (2 * K1_A_SZ + 2 * K1_B_SZ)  // 55296
#define K1_SMEM   (2 * K1_BUF)             // 110592

__global__ void __launch_bounds__(256, 2) k1_mma(const float* __restrict__ hidden) {
    extern __shared__ char smem[];
    const uint32_t sb = smem_u32(smem);
    const int tid = threadIdx.x, lane = tid & 31, wid = tid >> 5;
    const int b = blockIdx.y, s0 = blockIdx.x * 128;
    const int mrow0 = (wid >> 1) * 32, ncol0 = (wid & 1) * 32;
    const uint32_t rowoff = (lane & 7) + ((lane >> 3) & 1) * 8;
    const uint32_t coloff = (lane >> 4) * 8;
    const int g = lane >> 2, tg = lane & 3;

    const float* hbase = hidden + ((size_t)b * S_ + s0) * H_;

    float4 hv[8];
    float acc[2][4][4] = {};

    auto LDGA = [&](int ch) {
        const int h0 = ch * 64;
#pragma unroll
        for (int t = 0; t < 8; t++) {
            int idx = tid + t * 256, row = idx >> 4, f4 = idx & 15;
            hv[t] = *reinterpret_cast<const float4*>(hbase + (size_t)row * H_ + h0 + f4 * 4);
        }
    };

    auto CPB = [&](int ch, int buf) {
        const uint32_t bHi = sb + buf * K1_BUF + 2 * K1_A_SZ;
        const uint32_t bLo = bHi + K1_B_SZ;
        const int h0 = ch * 64;
#pragma unroll
        for (int t = 0; t < 2; t++) {
            int idx = tid + t * 256;          // 0..511
            int row = idx >> 3, k = idx & 7;
            uint32_t doff = row * K1_STRIDE + k * 16;
            const char* shi = reinterpret_cast<const char*>(g_qhi + (size_t)row * H_ + h0) + k * 16;
            const char* slo = reinterpret_cast<const char*>(g_qlo + (size_t)row * H_ + h0) + k * 16;
            cp16(bHi + doff, shi);
            cp16(bLo + doff, slo);
        }
        CP_COMMIT();
    };

    auto STSA = [&](int buf) {
        const uint32_t aHi = sb + buf * K1_BUF;
        const uint32_t aLo = aHi + K1_A_SZ;
#pragma unroll
        for (int t = 0; t < 8; t++) {
            int idx = tid + t * 256, row = idx >> 4, f4 = idx & 15;
            unsigned long long hh, ll;
            cvt_split(hv[t], hh, ll);
            uint32_t off = row * K1_STRIDE + f4 * 8;
            st64(aHi + off, hh);
            st64(aLo + off, ll);
        }
    };

    auto COMPUTE = [&](int buf) {
        const uint32_t aHi = sb + buf * K1_BUF;
        const uint32_t aLo = aHi + K1_A_SZ;
        const uint32_t bHi = aLo + K1_A_SZ;
        const uint32_t bLo = bHi + K1_B_SZ;
#pragma unroll
        for (int k16 = 0; k16 < 4; k16++) {
            const uint32_t kb = (k16 * 16 + coloff) * 2;
            uint32_t ah[2][4], al[2][4];
#pragma unroll
            for (int mi = 0; mi < 2; mi++) {
                uint32_t off = (mrow0 + mi * 16 + rowoff) * K1_STRIDE + kb;
                LDSM_X4(ah[mi][0], ah[mi][1], ah[mi][2], ah[mi][3], aHi + off);
                LDSM_X4(al[mi][0], al[mi][1], al[mi][2], al[mi][3], aLo + off);
            }
            uint32_t bh[4][2], bl[4][2];
#pragma unroll
            for (int nh = 0; nh < 2; nh++) {
                uint32_t off = (ncol0 + nh * 16 + rowoff) * K1_STRIDE + kb;
                uint32_t r0, r1, r2, r3;
                LDSM_X4(r0, r1, r2, r3, bHi + off);
                bh[nh * 2][0] = r0; bh[nh * 2][1] = r2;
                bh[nh * 2 + 1][0] = r1; bh[nh * 2 + 1][1] = r3;
                LDSM_X4(r0, r1, r2, r3, bLo + off);
                bl[nh * 2][0] = r0; bl[nh * 2][1] = r2;
                bl[nh * 2 + 1][0] = r1; bl[nh * 2 + 1][1] = r3;
            }
#pragma unroll
            for (int mi = 0; mi < 2; mi++)
#pragma unroll
                for (int ni = 0; ni < 4; ni++) {
                    MMA_BF16(acc[mi][ni], ah[mi], bh[ni][0], bh[ni][1]);
                    MMA_BF16(acc[mi][ni], ah[mi], bl[ni][0], bl[ni][1]);
                    MMA_BF16(acc[mi][ni], al[mi], bh[ni][0], bh[ni][1]);
                }
        }
    };

    // Prologue
    LDGA(0);
    CPB(0, 0);
    STSA(0);
    CP_WAIT0();
    __syncthreads();

#pragma unroll 1
    for (int ch = 0; ch < 16; ch++) {
        if (ch < 15) {
            CPB(ch + 1, (ch + 1) & 1);
            LDGA(ch + 1);
        }
        COMPUTE(ch & 1);
        if (ch < 15) STSA((ch + 1) & 1);
        CP_WAIT0();
        __syncthreads();
    }

    // Epilogue: transpose through smem -> coalesced [c][s] stores
    float* T = reinterpret_cast<float*>(smem);  // 64 x 132
#pragma unroll
    for (int mi = 0; mi < 2; mi++)
#pragma unroll
        for (int ni = 0; ni < 4; ni++) {
            int srow = mrow0 + mi * 16 + g;
            int ccol = ncol0 + ni * 8 + tg * 2;
            T[ccol * 132 + srow] = acc[mi][ni][0];
            T[(ccol + 1) * 132 + srow] = acc[mi][ni][1];
            T[ccol * 132 + srow + 8] = acc[mi][ni][2];
            T[(ccol + 1) * 132 + srow + 8] = acc[mi][ni][3];
        }
    __syncthreads();
    float* gs = g_scores + (size_t)b * C_ * S_ + s0;
#pragma unroll
    for (int t = 0; t < 8; t++) {
        int idx = tid + t * 256, row = idx >> 5, f4 = idx & 31;
        float4 v = *reinterpret_cast<const float4*>(&T[row * 132 + f4 * 4]);
        *reinterpret_cast<float4*>(gs + (size_t)row * S_ + f4 * 4) = v;
    }
}

// ===========================================================================
// K2: softmax over s for each of B*C rows; writes hi/lo bf16 factors.
// ===========================================================================
__global__ __launch_bounds__(256) void k2_softmax() {
    __shared__ float red_max[8];
    __shared__ float red_sum[8];

    const size_t rowoff = (size_t)blockIdx.x * S_;
    const float* row = g_scores + rowoff;
    const int tid = threadIdx.x;

    float4 v[4];
    float mx = -1e30f;
#pragma unroll
    for (int t = 0; t < 4; t++) {
        v[t] = reinterpret_cast<const float4*>(row)[tid + t * 256];
        mx = fmaxf(mx, fmaxf(fmaxf(v[t].x, v[t].y), fmaxf(v[t].z, v[t].w)));
    }
#pragma unroll
    for (int o = 16; o > 0; o >>= 1) mx = fmaxf(mx, __shfl_xor_sync(0xffffffffu, mx, o));
    if ((tid & 31) == 0) red_max[tid >> 5] = mx;
    __syncthreads();
    mx = red_max[0];
#pragma unroll
    for (int w = 1; w < 8; w++) mx = fmaxf(mx, red_max[w]);

    float s = 0.0f;
#pragma unroll
    for (int t = 0; t < 4; t++) {
        v[t].x = expf(v[t].x - mx);
        v[t].y = expf(v[t].y - mx);
        v[t].z = expf(v[t].z - mx);
        v[t].w = expf(v[t].w - mx);
        s += v[t].x + v[t].y + v[t].z + v[t].w;
    }
#pragma unroll
    for (int o = 16; o > 0; o >>= 1) s += __shfl_xor_sync(0xffffffffu, s, o);
    if ((tid & 31) == 0) red_sum[tid >> 5] = s;
    __syncthreads();
    s = red_sum[0];
#pragma unroll
    for (int w = 1; w < 8; w++) s += red_sum[w];

    const float inv = 1.0f / s;
#pragma unroll
    for (int t = 0; t < 4; t++) {
        v[t].x *= inv; v[t].y *= inv; v[t].z *= inv; v[t].w *= inv;
        unsigned long long hh, ll;
        cvt_split(v[t], hh, ll);
        size_t off = rowoff + (size_t)(tid + t * 256) * 4;
        *reinterpret_cast<unsigned long long*>(g_fhi + off) = hh;
        *reinterpret_cast<unsigned long long*>(g_flo + off) = ll;
    }
}

// ===========================================================================
// K3: out[b][c*H+h] = sum_s factor[b][c][s] * hidden[b][s][h]
// D[c,h]: M=64 c, N=64 h, K=4096 s (64 chunks of 64). grid = 16 x 16 = 256 CTAs.
// A = pre-split factors hi/lo via cp.async. B = hidden (LDG+cvt+STS, ldmatrix.trans).
// 8 warps as 4(m) x 2(n): warp tile 16 x 32.
// ===========================================================================
#define K3_STR  144                        // smem row stride bytes (72 bf16)
#define K3_A_SZ (64 * K3_STR)              // 9216
#define K3_B_SZ (64 * K3_STR)              // 9216
#define K3_BUF  (2 * K3_A_SZ + 2 * K3_B_SZ)   // 36864
#define K3_SMEM (2 * K3_BUF)               // 73728

__global__ void __launch_bounds__(256, 2) k3_mma(const float* __restrict__ hidden,
                                                 float* __restrict__ out) {
    extern __shared__ char smem[];
    const uint32_t sb = smem_u32(smem);
    const int tid = threadIdx.x, lane = tid & 31, wid = tid >> 5;
    const int b = blockIdx.y, h0 = blockIdx.x * 64;
    const int mrow0 = (wid >> 1) * 16, ncol0 = (wid & 1) * 32;
    const uint32_t rowoff = (lane & 7) + ((lane >> 3) & 1) * 8;
    const uint32_t coloff = (lane >> 4) * 8;
    const int g = lane >> 2, tg = lane & 3;

    const __nv_bfloat16* fhib = g_fhi + (size_t)b * C_ * S_;
    const __nv_bfloat16* flob = g_flo + (size_t)b * C_ * S_;
    const float* hbase = hidden + (size_t)b * S_ * H_;

    float4 hv[4];
    float acc[4][4] = {};

    auto CPA = [&](int ch, int buf) {
        const uint32_t aHi = sb + buf * K3_BUF;
        const uint32_t aLo = aHi + K3_A_SZ;
        const int s0 = ch * 64;
#pragma unroll
        for (int t = 0; t < 2; t++) {
            int idx = tid + t * 256;          // 0..511
            int row = idx >> 3, k = idx & 7;
            uint32_t doff = row * K3_STR + k * 16;
            const char* shi = reinterpret_cast<const char*>(fhib + (size_t)row * S_ + s0) + k * 16;
            const char* slo = reinterpret_cast<const char*>(flob + (size_t)row * S_ + s0) + k * 16;
            cp16(aHi + doff, shi);
            cp16(aLo + doff, slo);
        }
        CP_COMMIT();
    };

    auto LDGB = [&](int ch) {
        const int s0 = ch * 64;
#pragma unroll
        for (int t = 0; t < 4; t++) {
            int idx = tid + t * 256, row = idx >> 4, f4 = idx & 15;
            hv[t] = *reinterpret_cast<const float4*>(hbase + (size_t)(s0 + row) * H_ + h0 + f4 * 4);
        }
    };

    auto STSB = [&](int buf) {
        const uint32_t bHi = sb + buf * K3_BUF + 2 * K3_A_SZ;
        const uint32_t bLo = bHi + K3_B_SZ;
#pragma unroll
        for (int t = 0; t < 4; t++) {
            int idx = tid + t * 256, row = idx >> 4, f4 = idx & 15;
            unsigned long long hh, ll;
            cvt_split(hv[t], hh, ll);
            uint32_t off = row * K3_STR + f4 * 8;
            st64(bHi + off, hh);
            st64(bLo + off, ll);
        }
    };

    auto COMPUTE = [&](int buf) {
        const uint32_t aHi = sb + buf * K3_BUF;
        const uint32_t aLo = aHi + K3_A_SZ;
        const uint32_t bHi = aLo + K3_A_SZ;
        const uint32_t bLo = bHi + K3_B_SZ;
#pragma unroll
        for (int k16 = 0; k16 < 4; k16++) {
            uint32_t ah[4], al[4];
            {
                uint32_t off = (mrow0 + rowoff) * K3_STR + (k16 * 16 + coloff) * 2;
                LDSM_X4(ah[0], ah[1], ah[2], ah[3], aHi + off);
                LDSM_X4(al[0], al[1], al[2], al[3], aLo + off);
            }
            uint32_t bh[4][2], bl[4][2];
#pragma unroll
            for (int nh = 0; nh < 2; nh++) {
                uint32_t off = (k16 * 16 + rowoff) * K3_STR + (ncol0 + nh * 16 + coloff) * 2;
                uint32_t r0, r1, r2, r3;
                LDSM_X4T(r0, r1, r2, r3, bHi + off);
                bh[nh * 2][0] = r0; bh[nh * 2][1] = r1;
                bh[nh * 2 + 1][0] = r2; bh[nh * 2 + 1][1] = r3;
                LDSM_X4T(r0, r1, r2, r3, bLo + off);
                bl[nh * 2][0] = r0; bl[nh * 2][1] = r1;
                bl[nh * 2 + 1][0] = r2; bl[nh * 2 + 1][1] = r3;
            }
#pragma unroll
            for (int ni = 0; ni < 4; ni++) {
                MMA_BF16(acc[ni], ah, bh[ni][0], bh[ni][1]);
                MMA_BF16(acc[ni], ah, bl[ni][0], bl[ni][1]);
                MMA_BF16(acc[ni], al, bh[ni][0], bh[ni][1]);
            }
        }
    };

    // Prologue
    CPA(0, 0);
    LDGB(0);
    STSB(0);
    CP_WAIT0();
    __syncthreads();

#pragma unroll 1
    for (int ch = 0; ch < 64; ch++) {
        if (ch < 63) {
            CPA(ch + 1, (ch + 1) & 1);
            LDGB(ch + 1);
        }
        COMPUTE(ch & 1);
        if (ch < 63) STSB((ch + 1) & 1);
        CP_WAIT0();
        __syncthreads();
    }

    // Epilogue: direct float2 stores, out[b][c*H + h]
    float* ob = out + (size_t)b * (C_ * H_) + h0;
    const int crow = mrow0 + g;
#pragma unroll
    for (int ni = 0; ni < 4; ni++) {
        int hcol = ncol0 + ni * 8 + tg * 2;
        float2 v0 = make_float2(acc[ni][0], acc[ni][1]);
        float2 v1 = make_float2(acc[ni][2], acc[ni][3]);
        *reinterpret_cast<float2*>(ob + (size_t)crow * H_ + hcol) = v0;
        *reinterpret_cast<float2*>(ob + (size_t)(crow + 8) * H_ + hcol) = v1;
    }
}

// ---------------------------------------------------------------------------
extern "C" void kernel_launch(void* const* d_in, const int* in_sizes, int n_in,
                              void* d_out, int out_size) {
    const float* hidden = (const float*)d_in[0];   // [B, S, H] fp32
    const float* querys = (const float*)d_in[1];   // [C, H]    fp32
    float* out = (float*)d_out;                    // [B, C*H]  fp32

    cudaFuncSetAttribute(k1_mma, cudaFuncAttributeMaxDynamicSharedMemorySize, K1_SMEM);
    cudaFuncSetAttribute(k3_mma, cudaFuncAttributeMaxDynamicSharedMemorySize, K3_SMEM);

    k0_prep<<<C_, 256>>>(querys);

    dim3 g1(S_ / 128, B_);
    k1_mma<<<g1, 256, K1_SMEM>>>(hidden);

    k2_softmax<<<B_ * C_, 256>>>();

    dim3 g3(H_ / 64, B_);
    k3_mma<<<g3, 256, K3_SMEM>>>(hidden, out);
}

// round 7
// speedup vs baseline: 1.0996x; 1.0033x over previous
#include <cuda_runtime.h>
#include <cuda_bf16.h>
#include <cstdint>
#include <math.h>

#define B_ 16
#define S_ 4096
#define H_ 1024
#define C_ 64

// Scratch: fp32 scores, bf16 hi/lo factor arrays, bf16 hi/lo querys
__device__ __align__(16) float g_scores[B_ * C_ * S_];                // 16 MB
__device__ __align__(16) __nv_bfloat16 g_fhi[B_ * C_ * S_];           // 8 MB
__device__ __align__(16) __nv_bfloat16 g_flo[B_ * C_ * S_];           // 8 MB
__device__ __align__(16) __nv_bfloat16 g_qhi[C_ * H_];                // 128 KB
__device__ __align__(16) __nv_bfloat16 g_qlo[C_ * H_];                // 128 KB

// ===========================================================================
// Helpers
// ===========================================================================
__device__ __forceinline__ uint32_t smem_u32(const void* p) {
    uint32_t a;
    asm("{ .reg .u64 t; cvta.to.shared.u64 t, %1; cvt.u32.u64 %0, t; }"
        : "=r"(a) : "l"(p));
    return a;
}

// pack (f0 -> low half, f1 -> high half) as bf16x2
__device__ __forceinline__ uint32_t pack_bf2(float f0, float f1) {
    uint32_t r;
    asm("cvt.rn.bf16x2.f32 %0, %2, %1;" : "=r"(r) : "f"(f0), "f"(f1));
    return r;
}

// split float4 into hi-bf16x4 and lo-bf16x4 (lo = x - hi, rounded to bf16)
__device__ __forceinline__ void cvt_split(float4 v, unsigned long long& hh,
                                          unsigned long long& ll) {
    uint32_t h01 = pack_bf2(v.x, v.y);
    uint32_t h23 = pack_bf2(v.z, v.w);
    float l0 = v.x - __uint_as_float(h01 << 16);
    float l1 = v.y - __uint_as_float(h01 & 0xffff0000u);
    float l2 = v.z - __uint_as_float(h23 << 16);
    float l3 = v.w - __uint_as_float(h23 & 0xffff0000u);
    hh = ((unsigned long long)h23 << 32) | h01;
    ll = ((unsigned long long)pack_bf2(l2, l3) << 32) | pack_bf2(l0, l1);
}

__device__ __forceinline__ void st64(uint32_t a, unsigned long long v) {
    asm volatile("st.shared.b64 [%0], %1;" :: "r"(a), "l"(v) : "memory");
}

__device__ __forceinline__ void cp16(uint32_t dst, const void* src) {
    asm volatile("cp.async.cg.shared.global [%0], [%1], 16;"
                 :: "r"(dst), "l"(__cvta_generic_to_global(src)) : "memory");
}
#define CP_COMMIT() asm volatile("cp.async.commit_group;" ::: "memory")
#define CP_WAIT0()  asm volatile("cp.async.wait_group 0;" ::: "memory")

#define LDSM_X4(r0, r1, r2, r3, a) \
    asm volatile("ldmatrix.sync.aligned.m8n8.x4.shared.b16 {%0,%1,%2,%3}, [%4];" \
                 : "=r"(r0), "=r"(r1), "=r"(r2), "=r"(r3) : "r"(a))

#define LDSM_X4T(r0, r1, r2, r3, a) \
    asm volatile("ldmatrix.sync.aligned.m8n8.x4.trans.shared.b16 {%0,%1,%2,%3}, [%4];" \
                 : "=r"(r0), "=r"(r1), "=r"(r2), "=r"(r3) : "r"(a))

#define MMA_BF16(d, a, b0, b1) \
    asm volatile("mma.sync.aligned.m16n8k16.row.col.f32.bf16.bf16.f32 " \
                 "{%0,%1,%2,%3}, {%4,%5,%6,%7}, {%8,%9}, {%0,%1,%2,%3};" \
                 : "+f"((d)[0]), "+f"((d)[1]), "+f"((d)[2]), "+f"((d)[3]) \
                 : "r"((a)[0]), "r"((a)[1]), "r"((a)[2]), "r"((a)[3]), \
                   "r"(b0), "r"(b1))

// ===========================================================================
// K0: pre-split querys [C][H] fp32 -> hi/lo bf16
// ===========================================================================
__global__ __launch_bounds__(256) void k0_prep(const float* __restrict__ querys) {
    const int c = blockIdx.x;
    const int tid = threadIdx.x;
    float4 v = *reinterpret_cast<const float4*>(querys + (size_t)c * H_ + tid * 4);
    unsigned long long hh, ll;
    cvt_split(v, hh, ll);
    *reinterpret_cast<unsigned long long*>(g_qhi + (size_t)c * H_ + tid * 4) = hh;
    *reinterpret_cast<unsigned long long*>(g_qlo + (size_t)c * H_ + tid * 4) = ll;
}

// ===========================================================================
// K1: scores[b][c][s] = sum_h hidden[b][s][h] * querys[c][h]
// D[s,c]: M=128 s, N=64 c, K=1024 h (16 chunks of 64).
// A = hidden (LDG+cvt+STS). B = pre-split querys hi/lo via cp.async.
// MMA issue is TERM-MAJOR: all hh, then all hl, then all lh (spacing 8 per acc).
// ===========================================================================
#define K1_STRIDE 144                      // bytes per smem row (72 bf16)
#define K1_A_SZ   (128 * K1_STRIDE)        // 18432
#define K1_B_SZ   (64 * K1_STRIDE)         // 9216
#define K1_BUF    (2 * K1_A_SZ + 2 * K1_B_SZ)  // 55296
#define K1_SMEM   (2 * K1_BUF)             // 110592

__global__ void __launch_bounds__(256, 2) k1_mma(const float* __restrict__ hidden) {
    extern __shared__ char smem[];
    const uint32_t sb = smem_u32(smem);
    const int tid = threadIdx.x, lane = tid & 31, wid = tid >> 5;
    const int b = blockIdx.y, s0 = blockIdx.x * 128;
    const int mrow0 = (wid >> 1) * 32, ncol0 = (wid & 1) * 32;
    const uint32_t rowoff = (lane & 7) + ((lane >> 3) & 1) * 8;
    const uint32_t coloff = (lane >> 4) * 8;
    const int g = lane >> 2, tg = lane & 3;

    const float* hbase = hidden + ((size_t)b * S_ + s0) * H_;

    float4 hv[8];
    float acc[2][4][4] = {};

    auto LDGA = [&](int ch) {
        const int h0 = ch * 64;
#pragma unroll
        for (int t = 0; t < 8; t++) {
            int idx = tid + t * 256, row = idx >> 4, f4 = idx & 15;
            hv[t] = *reinterpret_cast<const float4*>(hbase + (size_t)row * H_ + h0 + f4 * 4);
        }
    };

    auto CPB = [&](int ch, int buf) {
        const uint32_t bHi = sb + buf * K1_BUF + 2 * K1_A_SZ;
        const uint32_t bLo = bHi + K1_B_SZ;
        const int h0 = ch * 64;
#pragma unroll
        for (int t = 0; t < 2; t++) {
            int idx = tid + t * 256;          // 0..511
            int row = idx >> 3, k = idx & 7;
            uint32_t doff = row * K1_STRIDE + k * 16;
            const char* shi = reinterpret_cast<const char*>(g_qhi + (size_t)row * H_ + h0) + k * 16;
            const char* slo = reinterpret_cast<const char*>(g_qlo + (size_t)row * H_ + h0) + k * 16;
            cp16(bHi + doff, shi);
            cp16(bLo + doff, slo);
        }
        CP_COMMIT();
    };

    auto STSA = [&](int buf) {
        const uint32_t aHi = sb + buf * K1_BUF;
        const uint32_t aLo = aHi + K1_A_SZ;
#pragma unroll
        for (int t = 0; t < 8; t++) {
            int idx = tid + t * 256, row = idx >> 4, f4 = idx & 15;
            unsigned long long hh, ll;
            cvt_split(hv[t], hh, ll);
            uint32_t off = row * K1_STRIDE + f4 * 8;
            st64(aHi + off, hh);
            st64(aLo + off, ll);
        }
    };

    auto COMPUTE = [&](int buf) {
        const uint32_t aHi = sb + buf * K1_BUF;
        const uint32_t aLo = aHi + K1_A_SZ;
        const uint32_t bHi = aLo + K1_A_SZ;
        const uint32_t bLo = bHi + K1_B_SZ;
#pragma unroll
        for (int k16 = 0; k16 < 4; k16++) {
            const uint32_t kb = (k16 * 16 + coloff) * 2;
            uint32_t ah[2][4], al[2][4];
#pragma unroll
            for (int mi = 0; mi < 2; mi++) {
                uint32_t off = (mrow0 + mi * 16 + rowoff) * K1_STRIDE + kb;
                LDSM_X4(ah[mi][0], ah[mi][1], ah[mi][2], ah[mi][3], aHi + off);
                LDSM_X4(al[mi][0], al[mi][1], al[mi][2], al[mi][3], aLo + off);
            }
            uint32_t bh[4][2], bl[4][2];
#pragma unroll
            for (int nh = 0; nh < 2; nh++) {
                uint32_t off = (ncol0 + nh * 16 + rowoff) * K1_STRIDE + kb;
                uint32_t r0, r1, r2, r3;
                LDSM_X4(r0, r1, r2, r3, bHi + off);
                bh[nh * 2][0] = r0; bh[nh * 2][1] = r2;
                bh[nh * 2 + 1][0] = r1; bh[nh * 2 + 1][1] = r3;
                LDSM_X4(r0, r1, r2, r3, bLo + off);
                bl[nh * 2][0] = r0; bl[nh * 2][1] = r2;
                bl[nh * 2 + 1][0] = r1; bl[nh * 2 + 1][1] = r3;
            }
            // Term-major: same-acc MMAs spaced by 8 independent MMAs
#pragma unroll
            for (int mi = 0; mi < 2; mi++)
#pragma unroll
                for (int ni = 0; ni < 4; ni++)
                    MMA_BF16(acc[mi][ni], ah[mi], bh[ni][0], bh[ni][1]);
#pragma unroll
            for (int mi = 0; mi < 2; mi++)
#pragma unroll
                for (int ni = 0; ni < 4; ni++)
                    MMA_BF16(acc[mi][ni], ah[mi], bl[ni][0], bl[ni][1]);
#pragma unroll
            for (int mi = 0; mi < 2; mi++)
#pragma unroll
                for (int ni = 0; ni < 4; ni++)
                    MMA_BF16(acc[mi][ni], al[mi], bh[ni][0], bh[ni][1]);
        }
    };

    // Prologue
    LDGA(0);
    CPB(0, 0);
    STSA(0);
    CP_WAIT0();
    __syncthreads();

#pragma unroll 1
    for (int ch = 0; ch < 16; ch++) {
        if (ch < 15) {
            CPB(ch + 1, (ch + 1) & 1);
            LDGA(ch + 1);
        }
        COMPUTE(ch & 1);
        if (ch < 15) STSA((ch + 1) & 1);
        CP_WAIT0();
        __syncthreads();
    }

    // Epilogue: transpose through smem -> coalesced [c][s] stores
    float* T = reinterpret_cast<float*>(smem);  // 64 x 132
#pragma unroll
    for (int mi = 0; mi < 2; mi++)
#pragma unroll
        for (int ni = 0; ni < 4; ni++) {
            int srow = mrow0 + mi * 16 + g;
            int ccol = ncol0 + ni * 8 + tg * 2;
            T[ccol * 132 + srow] = acc[mi][ni][0];
            T[(ccol + 1) * 132 + srow] = acc[mi][ni][1];
            T[ccol * 132 + srow + 8] = acc[mi][ni][2];
            T[(ccol + 1) * 132 + srow + 8] = acc[mi][ni][3];
        }
    __syncthreads();
    float* gs = g_scores + (size_t)b * C_ * S_ + s0;
#pragma unroll
    for (int t = 0; t < 8; t++) {
        int idx = tid + t * 256, row = idx >> 5, f4 = idx & 31;
        float4 v = *reinterpret_cast<const float4*>(&T[row * 132 + f4 * 4]);
        *reinterpret_cast<float4*>(gs + (size_t)row * S_ + f4 * 4) = v;
    }
}

// ===========================================================================
// K2: softmax over s for each of B*C rows; writes hi/lo bf16 factors.
// ===========================================================================
__global__ __launch_bounds__(256) void k2_softmax() {
    __shared__ float red_max[8];
    __shared__ float red_sum[8];

    const size_t rowoff = (size_t)blockIdx.x * S_;
    const float* row = g_scores + rowoff;
    const int tid = threadIdx.x;

    float4 v[4];
    float mx = -1e30f;
#pragma unroll
    for (int t = 0; t < 4; t++) {
        v[t] = reinterpret_cast<const float4*>(row)[tid + t * 256];
        mx = fmaxf(mx, fmaxf(fmaxf(v[t].x, v[t].y), fmaxf(v[t].z, v[t].w)));
    }
#pragma unroll
    for (int o = 16; o > 0; o >>= 1) mx = fmaxf(mx, __shfl_xor_sync(0xffffffffu, mx, o));
    if ((tid & 31) == 0) red_max[tid >> 5] = mx;
    __syncthreads();
    mx = red_max[0];
#pragma unroll
    for (int w = 1; w < 8; w++) mx = fmaxf(mx, red_max[w]);

    float s = 0.0f;
#pragma unroll
    for (int t = 0; t < 4; t++) {
        v[t].x = expf(v[t].x - mx);
        v[t].y = expf(v[t].y - mx);
        v[t].z = expf(v[t].z - mx);
        v[t].w = expf(v[t].w - mx);
        s += v[t].x + v[t].y + v[t].z + v[t].w;
    }
#pragma unroll
    for (int o = 16; o > 0; o >>= 1) s += __shfl_xor_sync(0xffffffffu, s, o);
    if ((tid & 31) == 0) red_sum[tid >> 5] = s;
    __syncthreads();
    s = red_sum[0];
#pragma unroll
    for (int w = 1; w < 8; w++) s += red_sum[w];

    const float inv = 1.0f / s;
#pragma unroll
    for (int t = 0; t < 4; t++) {
        v[t].x *= inv; v[t].y *= inv; v[t].z *= inv; v[t].w *= inv;
        unsigned long long hh, ll;
        cvt_split(v[t], hh, ll);
        size_t off = rowoff + (size_t)(tid + t * 256) * 4;
        *reinterpret_cast<unsigned long long*>(g_fhi + off) = hh;
        *reinterpret_cast<unsigned long long*>(g_flo + off) = ll;
    }
}

// ===========================================================================
// K3: out[b][c*H+h] = sum_s factor[b][c][s] * hidden[b][s][h]
// D[c,h]: M=64 c, N=64 h, K=4096 s (64 chunks of 64). grid = 16 x 16 = 256 CTAs.
// A = pre-split factors hi/lo via cp.async. B = hidden (LDG+cvt+STS, ldmatrix.trans).
// 8 warps as 4(m) x 2(n): warp tile 16 x 32. Term-major MMA issue (spacing 4).
// ===========================================================================
#define K3_STR  144                        // smem row stride bytes (72 bf16)
#define K3_A_SZ (64 * K3_STR)              // 9216
#define K3_B_SZ (64 * K3_STR)              // 9216
#define K3_BUF  (2 * K3_A_SZ + 2 * K3_B_SZ)   // 36864
#define K3_SMEM (2 * K3_BUF)               // 73728

__global__ void __launch_bounds__(256, 2) k3_mma(const float* __restrict__ hidden,
                                                 float* __restrict__ out) {
    extern __shared__ char smem[];
    const uint32_t sb = smem_u32(smem);
    const int tid = threadIdx.x, lane = tid & 31, wid = tid >> 5;
    const int b = blockIdx.y, h0 = blockIdx.x * 64;
    const int mrow0 = (wid >> 1) * 16, ncol0 = (wid & 1) * 32;
    const uint32_t rowoff = (lane & 7) + ((lane >> 3) & 1) * 8;
    const uint32_t coloff = (lane >> 4) * 8;
    const int g = lane >> 2, tg = lane & 3;

    const __nv_bfloat16* fhib = g_fhi + (size_t)b * C_ * S_;
    const __nv_bfloat16* flob = g_flo + (size_t)b * C_ * S_;
    const float* hbase = hidden + (size_t)b * S_ * H_;

    float4 hv[4];
    float acc[4][4] = {};

    auto CPA = [&](int ch, int buf) {
        const uint32_t aHi = sb + buf * K3_BUF;
        const uint32_t aLo = aHi + K3_A_SZ;
        const int s0 = ch * 64;
#pragma unroll
        for (int t = 0; t < 2; t++) {
            int idx = tid + t * 256;          // 0..511
            int row = idx >> 3, k = idx & 7;
            uint32_t doff = row * K3_STR + k * 16;
            const char* shi = reinterpret_cast<const char*>(fhib + (size_t)row * S_ + s0) + k * 16;
            const char* slo = reinterpret_cast<const char*>(flob + (size_t)row * S_ + s0) + k * 16;
            cp16(aHi + doff, shi);
            cp16(aLo + doff, slo);
        }
        CP_COMMIT();
    };

    auto LDGB = [&](int ch) {
        const int s0 = ch * 64;
#pragma unroll
        for (int t = 0; t < 4; t++) {
            int idx = tid + t * 256, row = idx >> 4, f4 = idx & 15;
            hv[t] = *reinterpret_cast<const float4*>(hbase + (size_t)(s0 + row) * H_ + h0 + f4 * 4);
        }
    };

    auto STSB = [&](int buf) {
        const uint32_t bHi = sb + buf * K3_BUF + 2 * K3_A_SZ;
        const uint32_t bLo = bHi + K3_B_SZ;
#pragma unroll
        for (int t = 0; t < 4; t++) {
            int idx = tid + t * 256, row = idx >> 4, f4 = idx & 15;
            unsigned long long hh, ll;
            cvt_split(hv[t], hh, ll);
            uint32_t off = row * K3_STR + f4 * 8;
            st64(bHi + off, hh);
            st64(bLo + off, ll);
        }
    };

    auto COMPUTE = [&](int buf) {
        const uint32_t aHi = sb + buf * K3_BUF;
        const uint32_t aLo = aHi + K3_A_SZ;
        const uint32_t bHi = aLo + K3_A_SZ;
        const uint32_t bLo = bHi + K3_B_SZ;
#pragma unroll
        for (int k16 = 0; k16 < 4; k16++) {
            uint32_t ah[4], al[4];
            {
                uint32_t off = (mrow0 + rowoff) * K3_STR + (k16 * 16 + coloff) * 2;
                LDSM_X4(ah[0], ah[1], ah[2], ah[3], aHi + off);
                LDSM_X4(al[0], al[1], al[2], al[3], aLo + off);
            }
            uint32_t bh[4][2], bl[4][2];
#pragma unroll
            for (int nh = 0; nh < 2; nh++) {
                uint32_t off = (k16 * 16 + rowoff) * K3_STR + (ncol0 + nh * 16 + coloff) * 2;
                uint32_t r0, r1, r2, r3;
                LDSM_X4T(r0, r1, r2, r3, bHi + off);
                bh[nh * 2][0] = r0; bh[nh * 2][1] = r1;
                bh[nh * 2 + 1][0] = r2; bh[nh * 2 + 1][1] = r3;
                LDSM_X4T(r0, r1, r2, r3, bLo + off);
                bl[nh * 2][0] = r0; bl[nh * 2][1] = r1;
                bl[nh * 2 + 1][0] = r2; bl[nh * 2 + 1][1] = r3;
            }
            // Term-major: same-acc MMAs spaced by 4 independent MMAs
#pragma unroll
            for (int ni = 0; ni < 4; ni++)
                MMA_BF16(acc[ni], ah, bh[ni][0], bh[ni][1]);
#pragma unroll
            for (int ni = 0; ni < 4; ni++)
                MMA_BF16(acc[ni], ah, bl[ni][0], bl[ni][1]);
#pragma unroll
            for (int ni = 0; ni < 4; ni++)
                MMA_BF16(acc[ni], al, bh[ni][0], bh[ni][1]);
        }
    };

    // Prologue
    CPA(0, 0);
    LDGB(0);
    STSB(0);
    CP_WAIT0();
    __syncthreads();

#pragma unroll 1
    for (int ch = 0; ch < 64; ch++) {
        if (ch < 63) {
            CPA(ch + 1, (ch + 1) & 1);
            LDGB(ch + 1);
        }
        COMPUTE(ch & 1);
        if (ch < 63) STSB((ch + 1) & 1);
        CP_WAIT0();
        __syncthreads();
    }

    // Epilogue: direct float2 stores, out[b][c*H + h]
    float* ob = out + (size_t)b * (C_ * H_) + h0;
    const int crow = mrow0 + g;
#pragma unroll
    for (int ni = 0; ni < 4; ni++) {
        int hcol = ncol0 + ni * 8 + tg * 2;
        float2 v0 = make_float2(acc[ni][0], acc[ni][1]);
        float2 v1 = make_float2(acc[ni][2], acc[ni][3]);
        *reinterpret_cast<float2*>(ob + (size_t)crow * H_ + hcol) = v0;
        *reinterpret_cast<float2*>(ob + (size_t)(crow + 8) * H_ + hcol) = v1;
    }
}

// ---------------------------------------------------------------------------
extern "C" void kernel_launch(void* const* d_in, const int* in_sizes, int n_in,
                              void* d_out, int out_size) {
    const float* hidden = (const float*)d_in[0];   // [B, S, H] fp32
    const float* querys = (const float*)d_in[1];   // [C, H]    fp32
    float* out = (float*)d_out;                    // [B, C*H]  fp32

    cudaFuncSetAttribute(k1_mma, cudaFuncAttributeMaxDynamicSharedMemorySize, K1_SMEM);
    cudaFuncSetAttribute(k3_mma, cudaFuncAttributeMaxDynamicSharedMemorySize, K3_SMEM);

    k0_prep<<<C_, 256>>>(querys);

    dim3 g1(S_ / 128, B_);
    k1_mma<<<g1, 256, K1_SMEM>>>(hidden);

    k2_softmax<<<B_ * C_, 256>>>();

    dim3 g3(H_ / 64, B_);
    k3_mma<<<g3, 256, K3_SMEM>>>(hidden, out);
}

// round 10
// speedup vs baseline: 1.2010x; 1.0922x over previous
#include <cuda_runtime.h>
#include <cuda_bf16.h>
#include <cstdint>
#include <math.h>

#define B_ 16
#define S_ 4096
#define H_ 1024
#define C_ 64

// Scratch: fp32 scores, bf16 hi/lo factor arrays, bf16 hi/lo querys
__device__ __align__(16) float g_scores[B_ * C_ * S_];                // 16 MB
__device__ __align__(16) __nv_bfloat16 g_fhi[B_ * C_ * S_];           // 8 MB
__device__ __align__(16) __nv_bfloat16 g_flo[B_ * C_ * S_];           // 8 MB
__device__ __align__(16) __nv_bfloat16 g_qhi[C_ * H_];                // 128 KB
__device__ __align__(16) __nv_bfloat16 g_qlo[C_ * H_];                // 128 KB

// ===========================================================================
// Helpers
// ===========================================================================
__device__ __forceinline__ uint32_t smem_u32(const void* p) {
    uint32_t a;
    asm("{ .reg .u64 t; cvta.to.shared.u64 t, %1; cvt.u32.u64 %0, t; }"
        : "=r"(a) : "l"(p));
    return a;
}

// pack (f0 -> low half, f1 -> high half) as bf16x2
__device__ __forceinline__ uint32_t pack_bf2(float f0, float f1) {
    uint32_t r;
    asm("cvt.rn.bf16x2.f32 %0, %2, %1;" : "=r"(r) : "f"(f0), "f"(f1));
    return r;
}

// split float4 into hi-bf16x4 and lo-bf16x4 (lo = x - hi, rounded to bf16)
__device__ __forceinline__ void cvt_split(float4 v, unsigned long long& hh,
                                          unsigned long long& ll) {
    uint32_t h01 = pack_bf2(v.x, v.y);
    uint32_t h23 = pack_bf2(v.z, v.w);
    float l0 = v.x - __uint_as_float(h01 << 16);
    float l1 = v.y - __uint_as_float(h01 & 0xffff0000u);
    float l2 = v.z - __uint_as_float(h23 << 16);
    float l3 = v.w - __uint_as_float(h23 & 0xffff0000u);
    hh = ((unsigned long long)h23 << 32) | h01;
    ll = ((unsigned long long)pack_bf2(l2, l3) << 32) | pack_bf2(l0, l1);
}

__device__ __forceinline__ void st64(uint32_t a, unsigned long long v) {
    asm volatile("st.shared.b64 [%0], %1;" :: "r"(a), "l"(v) : "memory");
}

__device__ __forceinline__ void cp16(uint32_t dst, const void* src) {
    asm volatile("cp.async.cg.shared.global [%0], [%1], 16;"
                 :: "r"(dst), "l"(__cvta_generic_to_global(src)) : "memory");
}
#define CP_COMMIT() asm volatile("cp.async.commit_group;" ::: "memory")
#define CP_WAIT0()  asm volatile("cp.async.wait_group 0;" ::: "memory")

#define LDSM_X4(r0, r1, r2, r3, a) \
    asm volatile("ldmatrix.sync.aligned.m8n8.x4.shared.b16 {%0,%1,%2,%3}, [%4];" \
                 : "=r"(r0), "=r"(r1), "=r"(r2), "=r"(r3) : "r"(a))

#define LDSM_X4T(r0, r1, r2, r3, a) \
    asm volatile("ldmatrix.sync.aligned.m8n8.x4.trans.shared.b16 {%0,%1,%2,%3}, [%4];" \
                 : "=r"(r0), "=r"(r1), "=r"(r2), "=r"(r3) : "r"(a))

#define MMA_BF16(d, a, b0, b1) \
    asm volatile("mma.sync.aligned.m16n8k16.row.col.f32.bf16.bf16.f32 " \
                 "{%0,%1,%2,%3}, {%4,%5,%6,%7}, {%8,%9}, {%0,%1,%2,%3};" \
                 : "+f"((d)[0]), "+f"((d)[1]), "+f"((d)[2]), "+f"((d)[3]) \
                 : "r"((a)[0]), "r"((a)[1]), "r"((a)[2]), "r"((a)[3]), \
                   "r"(b0), "r"(b1))

// Unified GEMM tile geometry: CTA 64x64, K-chunk 64, stride-144 smem rows.
#define G_STR   144                        // smem row stride bytes (72 bf16)
#define G_MAT   (64 * G_STR)               // 9216 bytes per 64x64 bf16 matrix
#define G_BUF   (4 * G_MAT)                // A-hi, A-lo, B-hi, B-lo = 36864
#define G_SMEM  (2 * G_BUF)                // 73728 (double-buffered)

// ===========================================================================
// K0: pre-split querys [C][H] fp32 -> hi/lo bf16
// ===========================================================================
__global__ __launch_bounds__(256) void k0_prep(const float* __restrict__ querys) {
    const int c = blockIdx.x;
    const int tid = threadIdx.x;
    float4 v = *reinterpret_cast<const float4*>(querys + (size_t)c * H_ + tid * 4);
    unsigned long long hh, ll;
    cvt_split(v, hh, ll);
    *reinterpret_cast<unsigned long long*>(g_qhi + (size_t)c * H_ + tid * 4) = hh;
    *reinterpret_cast<unsigned long long*>(g_qlo + (size_t)c * H_ + tid * 4) = ll;
}

// ===========================================================================
// K1: scores[b][c][s] = sum_h hidden[b][s][h] * querys[c][h]
// D[s,c]: CTA 64 s x 64 c, K=1024 h (16 chunks of 64). grid = 64 x 16 = 1024.
// 8 warps = (2m x 2n quadrants) x 2 k-halves; warp tile 32x32, k16 in {2kh,2kh+1}.
// A = hidden (LDG+cvt+STS). B = pre-split querys via cp.async (n-major, plain LDSM).
// ===========================================================================
__global__ void __launch_bounds__(256, 2) k1_mma(const float* __restrict__ hidden) {
    extern __shared__ char smem[];
    const uint32_t sb = smem_u32(smem);
    const int tid = threadIdx.x, lane = tid & 31, wid = tid >> 5;
    const int quad = wid & 3, kh = wid >> 2;
    const int m0 = (quad >> 1) * 32, n0 = (quad & 1) * 32;
    const int b = blockIdx.y, s0 = blockIdx.x * 64;
    const uint32_t rowoff = (lane & 7) + ((lane >> 3) & 1) * 8;
    const uint32_t coloff = (lane >> 4) * 8;
    const int g = lane >> 2, tg = lane & 3;

    const float* hbase = hidden + ((size_t)b * S_ + s0) * H_;

    float4 hv[4];
    float acc[2][4][4] = {};

    auto LDGA = [&](int ch) {
        const int h0 = ch * 64;
#pragma unroll
        for (int t = 0; t < 4; t++) {
            int idx = tid + t * 256, row = idx >> 4, f4 = idx & 15;
            hv[t] = *reinterpret_cast<const float4*>(hbase + (size_t)row * H_ + h0 + f4 * 4);
        }
    };

    auto CPB = [&](int ch, int buf) {
        const uint32_t bHi = sb + buf * G_BUF + 2 * G_MAT;
        const uint32_t bLo = bHi + G_MAT;
        const int h0 = ch * 64;
#pragma unroll
        for (int t = 0; t < 2; t++) {
            int idx = tid + t * 256;          // 0..511
            int row = idx >> 3, k = idx & 7;
            uint32_t doff = row * G_STR + k * 16;
            const char* shi = reinterpret_cast<const char*>(g_qhi + (size_t)row * H_ + h0) + k * 16;
            const char* slo = reinterpret_cast<const char*>(g_qlo + (size_t)row * H_ + h0) + k * 16;
            cp16(bHi + doff, shi);
            cp16(bLo + doff, slo);
        }
        CP_COMMIT();
    };

    auto STSA = [&](int buf) {
        const uint32_t aHi = sb + buf * G_BUF;
        const uint32_t aLo = aHi + G_MAT;
#pragma unroll
        for (int t = 0; t < 4; t++) {
            int idx = tid + t * 256, row = idx >> 4, f4 = idx & 15;
            unsigned long long hh, ll;
            cvt_split(hv[t], hh, ll);
            uint32_t off = row * G_STR + f4 * 8;
            st64(aHi + off, hh);
            st64(aLo + off, ll);
        }
    };

    auto COMPUTE = [&](int buf) {
        const uint32_t aHi = sb + buf * G_BUF;
        const uint32_t aLo = aHi + G_MAT;
        const uint32_t bHi = aLo + G_MAT;
        const uint32_t bLo = bHi + G_MAT;
#pragma unroll
        for (int kk = 0; kk < 2; kk++) {
            const int k16 = 2 * kh + kk;
            const uint32_t kb = (k16 * 16 + coloff) * 2;
            uint32_t ah[2][4], al[2][4];
#pragma unroll
            for (int mi = 0; mi < 2; mi++) {
                uint32_t off = (m0 + mi * 16 + rowoff) * G_STR + kb;
                LDSM_X4(ah[mi][0], ah[mi][1], ah[mi][2], ah[mi][3], aHi + off);
                LDSM_X4(al[mi][0], al[mi][1], al[mi][2], al[mi][3], aLo + off);
            }
            uint32_t bh[4][2], bl[4][2];
#pragma unroll
            for (int nh = 0; nh < 2; nh++) {
                uint32_t off = (n0 + nh * 16 + rowoff) * G_STR + kb;
                uint32_t r0, r1, r2, r3;
                LDSM_X4(r0, r1, r2, r3, bHi + off);
                bh[nh * 2][0] = r0; bh[nh * 2][1] = r2;
                bh[nh * 2 + 1][0] = r1; bh[nh * 2 + 1][1] = r3;
                LDSM_X4(r0, r1, r2, r3, bLo + off);
                bl[nh * 2][0] = r0; bl[nh * 2][1] = r2;
                bl[nh * 2 + 1][0] = r1; bl[nh * 2 + 1][1] = r3;
            }
#pragma unroll
            for (int mi = 0; mi < 2; mi++)
#pragma unroll
                for (int ni = 0; ni < 4; ni++)
                    MMA_BF16(acc[mi][ni], ah[mi], bh[ni][0], bh[ni][1]);
#pragma unroll
            for (int mi = 0; mi < 2; mi++)
#pragma unroll
                for (int ni = 0; ni < 4; ni++)
                    MMA_BF16(acc[mi][ni], ah[mi], bl[ni][0], bl[ni][1]);
#pragma unroll
            for (int mi = 0; mi < 2; mi++)
#pragma unroll
                for (int ni = 0; ni < 4; ni++)
                    MMA_BF16(acc[mi][ni], al[mi], bh[ni][0], bh[ni][1]);
        }
    };

    // Prologue
    LDGA(0);
    CPB(0, 0);
    STSA(0);
    CP_WAIT0();
    __syncthreads();

#pragma unroll 1
    for (int ch = 0; ch < 16; ch++) {
        if (ch < 15) {
            CPB(ch + 1, (ch + 1) & 1);
            LDGA(ch + 1);
        }
        COMPUTE(ch & 1);
        if (ch < 15) STSA((ch + 1) & 1);
        CP_WAIT0();
        __syncthreads();
    }

    // K-half reduction: kh=1 warps dump accs, kh=0 warps add.
    float* R = reinterpret_cast<float*>(smem);   // 4 quads x 32 lanes x 32 = 16KB
    if (kh == 1) {
#pragma unroll
        for (int mi = 0; mi < 2; mi++)
#pragma unroll
            for (int ni = 0; ni < 4; ni++)
#pragma unroll
                for (int e = 0; e < 4; e++)
                    R[quad * 1024 + lane * 32 + (mi * 4 + ni) * 4 + e] = acc[mi][ni][e];
    }
    __syncthreads();
    if (kh == 0) {
#pragma unroll
        for (int mi = 0; mi < 2; mi++)
#pragma unroll
            for (int ni = 0; ni < 4; ni++)
#pragma unroll
                for (int e = 0; e < 4; e++)
                    acc[mi][ni][e] += R[quad * 1024 + lane * 32 + (mi * 4 + ni) * 4 + e];
    }
    __syncthreads();

    // Epilogue: kh=0 warps transpose through smem -> coalesced [c][s] stores
    float* T = reinterpret_cast<float*>(smem);   // 64 c x 68 pad
    if (kh == 0) {
#pragma unroll
        for (int mi = 0; mi < 2; mi++)
#pragma unroll
            for (int ni = 0; ni < 4; ni++) {
                int srow = m0 + mi * 16 + g;
                int ccol = n0 + ni * 8 + tg * 2;
                T[ccol * 68 + srow] = acc[mi][ni][0];
                T[(ccol + 1) * 68 + srow] = acc[mi][ni][1];
                T[ccol * 68 + srow + 8] = acc[mi][ni][2];
                T[(ccol + 1) * 68 + srow + 8] = acc[mi][ni][3];
            }
    }
    __syncthreads();
    float* gs = g_scores + (size_t)b * C_ * S_ + s0;
#pragma unroll
    for (int t = 0; t < 4; t++) {
        int idx = tid + t * 256, row = idx >> 4, f4 = idx & 15;
        float4 v = *reinterpret_cast<const float4*>(&T[row * 68 + f4 * 4]);
        *reinterpret_cast<float4*>(gs + (size_t)row * S_ + f4 * 4) = v;
    }
}

// ===========================================================================
// K2: softmax over s for each of B*C rows; writes hi/lo bf16 factors.
// ===========================================================================
__global__ __launch_bounds__(256) void k2_softmax() {
    __shared__ float red_max[8];
    __shared__ float red_sum[8];

    const size_t rowoff = (size_t)blockIdx.x * S_;
    const float* row = g_scores + rowoff;
    const int tid = threadIdx.x;

    float4 v[4];
    float mx = -1e30f;
#pragma unroll
    for (int t = 0; t < 4; t++) {
        v[t] = reinterpret_cast<const float4*>(row)[tid + t * 256];
        mx = fmaxf(mx, fmaxf(fmaxf(v[t].x, v[t].y), fmaxf(v[t].z, v[t].w)));
    }
#pragma unroll
    for (int o = 16; o > 0; o >>= 1) mx = fmaxf(mx, __shfl_xor_sync(0xffffffffu, mx, o));
    if ((tid & 31) == 0) red_max[tid >> 5] = mx;
    __syncthreads();
    mx = red_max[0];
#pragma unroll
    for (int w = 1; w < 8; w++) mx = fmaxf(mx, red_max[w]);

    float s = 0.0f;
#pragma unroll
    for (int t = 0; t < 4; t++) {
        v[t].x = expf(v[t].x - mx);
        v[t].y = expf(v[t].y - mx);
        v[t].z = expf(v[t].z - mx);
        v[t].w = expf(v[t].w - mx);
        s += v[t].x + v[t].y + v[t].z + v[t].w;
    }
#pragma unroll
    for (int o = 16; o > 0; o >>= 1) s += __shfl_xor_sync(0xffffffffu, s, o);
    if ((tid & 31) == 0) red_sum[tid >> 5] = s;
    __syncthreads();
    s = red_sum[0];
#pragma unroll
    for (int w = 1; w < 8; w++) s += red_sum[w];

    const float inv = 1.0f / s;
#pragma unroll
    for (int t = 0; t < 4; t++) {
        v[t].x *= inv; v[t].y *= inv; v[t].z *= inv; v[t].w *= inv;
        unsigned long long hh, ll;
        cvt_split(v[t], hh, ll);
        size_t off = rowoff + (size_t)(tid + t * 256) * 4;
        *reinterpret_cast<unsigned long long*>(g_fhi + off) = hh;
        *reinterpret_cast<unsigned long long*>(g_flo + off) = ll;
    }
}

// ===========================================================================
// K3: out[b][c*H+h] = sum_s factor[b][c][s] * hidden[b][s][h]
// D[c,h]: CTA 64 c x 64 h, K=4096 s (64 chunks of 64). grid = 16 x 16 = 256.
// 8 warps = (2m x 2n quadrants) x 2 k-halves; warp tile 32x32, k16 in {2kh,2kh+1}.
// A = pre-split factors via cp.async. B = hidden (LDG+cvt+STS, ldmatrix.trans).
// ===========================================================================
__global__ void __launch_bounds__(256, 2) k3_mma(const float* __restrict__ hidden,
                                                 float* __restrict__ out) {
    extern __shared__ char smem[];
    const uint32_t sb = smem_u32(smem);
    const int tid = threadIdx.x, lane = tid & 31, wid = tid >> 5;
    const int quad = wid & 3, kh = wid >> 2;
    const int m0 = (quad >> 1) * 32, n0 = (quad & 1) * 32;
    const int b = blockIdx.y, h0 = blockIdx.x * 64;
    const uint32_t rowoff = (lane & 7) + ((lane >> 3) & 1) * 8;
    const uint32_t coloff = (lane >> 4) * 8;
    const int g = lane >> 2, tg = lane & 3;

    const __nv_bfloat16* fhib = g_fhi + (size_t)b * C_ * S_;
    const __nv_bfloat16* flob = g_flo + (size_t)b * C_ * S_;
    const float* hbase = hidden + (size_t)b * S_ * H_;

    float4 hv[4];
    float acc[2][4][4] = {};

    auto CPA = [&](int ch, int buf) {
        const uint32_t aHi = sb + buf * G_BUF;
        const uint32_t aLo = aHi + G_MAT;
        const int s0 = ch * 64;
#pragma unroll
        for (int t = 0; t < 2; t++) {
            int idx = tid + t * 256;          // 0..511
            int row = idx >> 3, k = idx & 7;
            uint32_t doff = row * G_STR + k * 16;
            const char* shi = reinterpret_cast<const char*>(fhib + (size_t)row * S_ + s0) + k * 16;
            const char* slo = reinterpret_cast<const char*>(flob + (size_t)row * S_ + s0) + k * 16;
            cp16(aHi + doff, shi);
            cp16(aLo + doff, slo);
        }
        CP_COMMIT();
    };

    auto LDGB = [&](int ch) {
        const int s0 = ch * 64;
#pragma unroll
        for (int t = 0; t < 4; t++) {
            int idx = tid + t * 256, row = idx >> 4, f4 = idx & 15;
            hv[t] = *reinterpret_cast<const float4*>(hbase + (size_t)(s0 + row) * H_ + h0 + f4 * 4);
        }
    };

    auto STSB = [&](int buf) {
        const uint32_t bHi = sb + buf * G_BUF + 2 * G_MAT;
        const uint32_t bLo = bHi + G_MAT;
#pragma unroll
        for (int t = 0; t < 4; t++) {
            int idx = tid + t * 256, row = idx >> 4, f4 = idx & 15;
            unsigned long long hh, ll;
            cvt_split(hv[t], hh, ll);
            uint32_t off = row * G_STR + f4 * 8;
            st64(bHi + off, hh);
            st64(bLo + off, ll);
        }
    };

    auto COMPUTE = [&](int buf) {
        const uint32_t aHi = sb + buf * G_BUF;
        const uint32_t aLo = aHi + G_MAT;
        const uint32_t bHi = aLo + G_MAT;
        const uint32_t bLo = bHi + G_MAT;
#pragma unroll
        for (int kk = 0; kk < 2; kk++) {
            const int k16 = 2 * kh + kk;
            uint32_t ah[2][4], al[2][4];
#pragma unroll
            for (int mi = 0; mi < 2; mi++) {
                uint32_t off = (m0 + mi * 16 + rowoff) * G_STR + (k16 * 16 + coloff) * 2;
                LDSM_X4(ah[mi][0], ah[mi][1], ah[mi][2], ah[mi][3], aHi + off);
                LDSM_X4(al[mi][0], al[mi][1], al[mi][2], al[mi][3], aLo + off);
            }
            uint32_t bh[4][2], bl[4][2];
#pragma unroll
            for (int nh = 0; nh < 2; nh++) {
                uint32_t off = (k16 * 16 + rowoff) * G_STR + (n0 + nh * 16 + coloff) * 2;
                uint32_t r0, r1, r2, r3;
                LDSM_X4T(r0, r1, r2, r3, bHi + off);
                bh[nh * 2][0] = r0; bh[nh * 2][1] = r1;
                bh[nh * 2 + 1][0] = r2; bh[nh * 2 + 1][1] = r3;
                LDSM_X4T(r0, r1, r2, r3, bLo + off);
                bl[nh * 2][0] = r0; bl[nh * 2][1] = r1;
                bl[nh * 2 + 1][0] = r2; bl[nh * 2 + 1][1] = r3;
            }
#pragma unroll
            for (int mi = 0; mi < 2; mi++)
#pragma unroll
                for (int ni = 0; ni < 4; ni++)
                    MMA_BF16(acc[mi][ni], ah[mi], bh[ni][0], bh[ni][1]);
#pragma unroll
            for (int mi = 0; mi < 2; mi++)
#pragma unroll
                for (int ni = 0; ni < 4; ni++)
                    MMA_BF16(acc[mi][ni], ah[mi], bl[ni][0], bl[ni][1]);
#pragma unroll
            for (int mi = 0; mi < 2; mi++)
#pragma unroll
                for (int ni = 0; ni < 4; ni++)
                    MMA_BF16(acc[mi][ni], al[mi], bh[ni][0], bh[ni][1]);
        }
    };

    // Prologue
    CPA(0, 0);
    LDGB(0);
    STSB(0);
    CP_WAIT0();
    __syncthreads();

#pragma unroll 1
    for (int ch = 0; ch < 64; ch++) {
        if (ch < 63) {
            CPA(ch + 1, (ch + 1) & 1);
            LDGB(ch + 1);
        }
        COMPUTE(ch & 1);
        if (ch < 63) STSB((ch + 1) & 1);
        CP_WAIT0();
        __syncthreads();
    }

    // K-half reduction: kh=1 warps dump accs, kh=0 warps add.
    float* R = reinterpret_cast<float*>(smem);
    if (kh == 1) {
#pragma unroll
        for (int mi = 0; mi < 2; mi++)
#pragma unroll
            for (int ni = 0; ni < 4; ni++)
#pragma unroll
                for (int e = 0; e < 4; e++)
                    R[quad * 1024 + lane * 32 + (mi * 4 + ni) * 4 + e] = acc[mi][ni][e];
    }
    __syncthreads();

    // Epilogue: kh=0 warps direct float2 stores, out[b][c*H + h]
    if (kh == 0) {
#pragma unroll
        for (int mi = 0; mi < 2; mi++)
#pragma unroll
            for (int ni = 0; ni < 4; ni++)
#pragma unroll
                for (int e = 0; e < 4; e++)
                    acc[mi][ni][e] += R[quad * 1024 + lane * 32 + (mi * 4 + ni) * 4 + e];

        float* ob = out + (size_t)b * (C_ * H_) + h0;
#pragma unroll
        for (int mi = 0; mi < 2; mi++) {
            int crow = m0 + mi * 16 + g;
#pragma unroll
            for (int ni = 0; ni < 4; ni++) {
                int hcol = n0 + ni * 8 + tg * 2;
                float2 v0 = make_float2(acc[mi][ni][0], acc[mi][ni][1]);
                float2 v1 = make_float2(acc[mi][ni][2], acc[mi][ni][3]);
                *reinterpret_cast<float2*>(ob + (size_t)crow * H_ + hcol) = v0;
                *reinterpret_cast<float2*>(ob + (size_t)(crow + 8) * H_ + hcol) = v1;
            }
        }
    }
}

// ---------------------------------------------------------------------------
extern "C" void kernel_launch(void* const* d_in, const int* in_sizes, int n_in,
                              void* d_out, int out_size) {
    const float* hidden = (const float*)d_in[0];   // [B, S, H] fp32
    const float* querys = (const float*)d_in[1];   // [C, H]    fp32
    float* out = (float*)d_out;                    // [B, C*H]  fp32

    cudaFuncSetAttribute(k1_mma, cudaFuncAttributeMaxDynamicSharedMemorySize, G_SMEM);
    cudaFuncSetAttribute(k3_mma, cudaFuncAttributeMaxDynamicSharedMemorySize, G_SMEM);

    k0_prep<<<C_, 256>>>(querys);

    dim3 g1(S_ / 64, B_);
    k1_mma<<<g1, 256, G_SMEM>>>(hidden);

    k2_softmax<<<B_ * C_, 256>>>();

    dim3 g3(H_ / 64, B_);
    k3_mma<<<g3, 256, G_SMEM>>>(hidden, out);
}